// round 9
// baseline (speedup 1.0000x reference)
#include <cuda_runtime.h>
#include <cuda_fp16.h>

#define IN_DIM 128
#define HIDD   128
#define OUTD   40
#define MAXN   50000
#define MAXE   800000
#define SCAN_B 256

// ---------------- scratch (device globals: allocation-free) ----------------
// g_degi is zero-initialized at module load and re-zeroed by scan_p3 each call
// (self-cleaning), so every graph replay sees a zeroed histogram.
static __device__ __half g_ywh[MAXN * HIDD];  // fp16: dinv * (x @ W1)
static __device__ float  g_h [MAXN * HIDD];   // fp32: layer-1 output (post ReLU)
static __device__ __half g_owh[MAXN * OUTD];  // fp16: dinv * (h @ W2)
static __device__ int    g_degi[MAXN];
static __device__ float  g_dinv[MAXN];
static __device__ int    g_rs  [MAXN + 1];
static __device__ int    g_cur [MAXN];
static __device__ int    g_col [MAXE];
static __device__ int    g_bsum[(MAXN + SCAN_B - 1) / SCAN_B + 1];

// ---------------- inline per-warp dtype detection ----------------
__device__ __forceinline__ int detect_is64_warp(const int* __restrict__ ei32) {
    int lane = threadIdx.x & 31;
    int v = ei32[1 + 2 * lane];
    unsigned any = __ballot_sync(0xffffffffu, v != 0);
    return any == 0 ? 1 : 0;
}

__device__ __forceinline__ int get_idx(const void* ei, long long pos, int is64) {
    return is64 ? (int)((const long long*)ei)[pos] : ((const int*)ei)[pos];
}

// ---------------- degree histogram (inline detect) ----------------
__global__ void deg_kernel(const void* __restrict__ ei, int E) {
    int is64 = detect_is64_warp((const int*)ei);
    int e = blockIdx.x * blockDim.x + threadIdx.x;
    if (e >= E) return;
    int d = get_idx(ei, (long long)E + e, is64);
    atomicAdd(&g_degi[d], 1);
}

// ---------------- scan phase 1: per-block sums ----------------
__global__ void scan_p1_kernel(int N) {
    int i = blockIdx.x * blockDim.x + threadIdx.x;
    int v = (i < N) ? g_degi[i] : 0;
    int lane = threadIdx.x & 31, wid = threadIdx.x >> 5;
#pragma unroll
    for (int o = 16; o > 0; o >>= 1) v += __shfl_xor_sync(0xffffffffu, v, o);
    __shared__ int ws[SCAN_B / 32];
    if (lane == 0) ws[wid] = v;
    __syncthreads();
    if (threadIdx.x == 0) {
        int s = 0;
#pragma unroll
        for (int w = 0; w < SCAN_B / 32; w++) s += ws[w];
        g_bsum[blockIdx.x] = s;
    }
}

// ---------------- scan phase 2+3 fused ----------------
__global__ void scan_p3_kernel(int N, int E) {
    int i = blockIdx.x * blockDim.x + threadIdx.x;
    int v = (i < N) ? g_degi[i] : 0;
    int lane = threadIdx.x & 31, wid = threadIdx.x >> 5;

    __shared__ int ws[32];
    __shared__ int s_off;
    if (threadIdx.x < 32) ws[threadIdx.x] = 0;
    if (threadIdx.x == 0) s_off = 0;
    __syncthreads();

    int x = v;
#pragma unroll
    for (int o = 1; o < 32; o <<= 1) {
        int u = __shfl_up_sync(0xffffffffu, x, o);
        if (lane >= o) x += u;
    }
    if (lane == 31) ws[wid] = x;
    __syncthreads();

    if (wid == 0) {
        int w = ws[lane];
#pragma unroll
        for (int o = 1; o < 32; o <<= 1) {
            int u = __shfl_up_sync(0xffffffffu, w, o);
            if (lane >= o) w += u;
        }
        ws[lane] = w;
    } else if (wid == 1) {
        int off = 0;
        for (int j = lane; j < (int)blockIdx.x; j += 32) off += g_bsum[j];
#pragma unroll
        for (int o = 16; o > 0; o >>= 1)
            off += __shfl_xor_sync(0xffffffffu, off, o);
        if (lane == 0) s_off = off;
    }
    __syncthreads();

    int excl = x - v + (wid > 0 ? ws[wid - 1] : 0) + s_off;
    if (i < N) {
        g_rs[i]   = excl;
        g_cur[i]  = excl;
        g_dinv[i] = rsqrtf((float)(v + 1));   // +1 self loop
        g_degi[i] = 0;                        // self-clean for next replay
    }
    if (i == 0) g_rs[N] = E;
}

// ---------------- scatter: build CSR column array ----------------
__global__ void scatter_kernel(const void* __restrict__ ei, int E) {
    int is64 = detect_is64_warp((const int*)ei);
    int e = blockIdx.x * blockDim.x + threadIdx.x;
    if (e >= E) return;
    int s = get_idx(ei, e, is64);
    int d = get_idx(ei, (long long)E + e, is64);
    int pos = atomicAdd(&g_cur[d], 1);
    g_col[pos] = s;
}

// ---------------- tf32 helpers ----------------
__device__ __forceinline__ unsigned f2tf(float f) {
    unsigned u;
    asm("cvt.rna.tf32.f32 %0, %1;" : "=r"(u) : "f"(f));
    return u;
}

// ---------------- TF32 GEMM1 (512 thr, 16 warps x [16 rows x 64 cols]) ------
// g_ywh = half( dinv[r] * (A[M,128] @ B[128,128]) )
__global__ void __launch_bounds__(512) gemm1_tc_kernel(const float* __restrict__ A,
                                                       const float* __restrict__ B,
                                                       __half* __restrict__ C, int M) {
    __shared__ unsigned As[32][136];   // [k][row]
    __shared__ unsigned Bs[32][136];   // [k][n]

    const int tid  = threadIdx.x;
    const int wid  = tid >> 5;
    const int lane = tid & 31;
    const int g    = lane >> 2;
    const int t    = lane & 3;
    const int wr   = wid & 7;          // row-group (16 rows)
    const int wn   = wid >> 3;         // n-half (64 cols)
    const int row0 = blockIdx.x * 128;

    float c[8][4];
#pragma unroll
    for (int j = 0; j < 8; j++)
#pragma unroll
        for (int q = 0; q < 4; q++) c[j][q] = 0.0f;

    for (int k0 = 0; k0 < 128; k0 += 32) {
#pragma unroll
        for (int f = 0; f < 2; f++) {
            int l4  = tid + f * 512;          // 0..1023 float4 slots
            int row = l4 >> 3;
            int kq  = (l4 & 7) * 4;
            float4 v = make_float4(0.f, 0.f, 0.f, 0.f);
            if (row0 + row < M)
                v = *(const float4*)(A + (size_t)(row0 + row) * 128 + k0 + kq);
            As[kq + 0][row] = f2tf(v.x);
            As[kq + 1][row] = f2tf(v.y);
            As[kq + 2][row] = f2tf(v.z);
            As[kq + 3][row] = f2tf(v.w);

            int bk = l4 >> 5;
            int bn = (l4 & 31) * 4;
            float4 w = *(const float4*)(B + (size_t)(k0 + bk) * 128 + bn);
            Bs[bk][bn + 0] = f2tf(w.x);
            Bs[bk][bn + 1] = f2tf(w.y);
            Bs[bk][bn + 2] = f2tf(w.z);
            Bs[bk][bn + 3] = f2tf(w.w);
        }
        __syncthreads();

#pragma unroll
        for (int kk = 0; kk < 4; kk++) {
            unsigned a0 = As[kk * 8 + t    ][wr * 16 + g    ];
            unsigned a1 = As[kk * 8 + t    ][wr * 16 + g + 8];
            unsigned a2 = As[kk * 8 + t + 4][wr * 16 + g    ];
            unsigned a3 = As[kk * 8 + t + 4][wr * 16 + g + 8];
#pragma unroll
            for (int j = 0; j < 8; j++) {
                unsigned b0 = Bs[kk * 8 + t    ][wn * 64 + j * 8 + g];
                unsigned b1 = Bs[kk * 8 + t + 4][wn * 64 + j * 8 + g];
                asm volatile(
                    "mma.sync.aligned.m16n8k8.row.col.f32.tf32.tf32.f32 "
                    "{%0,%1,%2,%3}, {%4,%5,%6,%7}, {%8,%9}, {%0,%1,%2,%3};"
                    : "+f"(c[j][0]), "+f"(c[j][1]), "+f"(c[j][2]), "+f"(c[j][3])
                    : "r"(a0), "r"(a1), "r"(a2), "r"(a3), "r"(b0), "r"(b1));
            }
        }
        __syncthreads();
    }

    int r1 = row0 + wr * 16 + g;
    int r2 = r1 + 8;
    float d1 = (r1 < M) ? g_dinv[r1] : 0.0f;
    float d2 = (r2 < M) ? g_dinv[r2] : 0.0f;
#pragma unroll
    for (int j = 0; j < 8; j++) {
        int n = wn * 64 + j * 8 + t * 2;
        if (r1 < M)
            *(__half2*)(C + (size_t)r1 * 128 + n) = __floats2half2_rn(c[j][0] * d1, c[j][1] * d1);
        if (r2 < M)
            *(__half2*)(C + (size_t)r2 * 128 + n) = __floats2half2_rn(c[j][2] * d2, c[j][3] * d2);
    }
}

// ---------------- TF32 GEMM2: g_owh = half( dinv[r] * (h[M,128] @ W2[128,40]) )
__global__ void __launch_bounds__(256) gemm2_tc_kernel(const float* __restrict__ A,
                                                       const float* __restrict__ B,
                                                       __half* __restrict__ C, int M) {
    __shared__ unsigned As[32][136];   // [k][row], per 32-k chunk
    __shared__ unsigned Bs[128][48];   // full B [k][n], staged once

    const int tid  = threadIdx.x;
    const int wid  = tid >> 5;
    const int lane = tid & 31;
    const int g    = lane >> 2;
    const int t    = lane & 3;
    const int row0 = blockIdx.x * 128;

    for (int i = tid; i < 128 * OUTD; i += 256) {
        int k = i / OUTD, n = i - k * OUTD;
        Bs[k][n] = f2tf(B[(size_t)k * OUTD + n]);
    }

    float c[5][4];
#pragma unroll
    for (int j = 0; j < 5; j++)
#pragma unroll
        for (int q = 0; q < 4; q++) c[j][q] = 0.0f;

    for (int k0 = 0; k0 < 128; k0 += 32) {
#pragma unroll
        for (int f = 0; f < 4; f++) {
            int l4  = tid + f * 256;
            int row = l4 >> 3;
            int kq  = (l4 & 7) * 4;
            float4 v = make_float4(0.f, 0.f, 0.f, 0.f);
            if (row0 + row < M)
                v = *(const float4*)(A + (size_t)(row0 + row) * 128 + k0 + kq);
            As[kq + 0][row] = f2tf(v.x);
            As[kq + 1][row] = f2tf(v.y);
            As[kq + 2][row] = f2tf(v.z);
            As[kq + 3][row] = f2tf(v.w);
        }
        __syncthreads();

#pragma unroll
        for (int kk = 0; kk < 4; kk++) {
            unsigned a0 = As[kk * 8 + t    ][wid * 16 + g    ];
            unsigned a1 = As[kk * 8 + t    ][wid * 16 + g + 8];
            unsigned a2 = As[kk * 8 + t + 4][wid * 16 + g    ];
            unsigned a3 = As[kk * 8 + t + 4][wid * 16 + g + 8];
#pragma unroll
            for (int j = 0; j < 5; j++) {
                unsigned b0 = Bs[k0 + kk * 8 + t    ][j * 8 + g];
                unsigned b1 = Bs[k0 + kk * 8 + t + 4][j * 8 + g];
                asm volatile(
                    "mma.sync.aligned.m16n8k8.row.col.f32.tf32.tf32.f32 "
                    "{%0,%1,%2,%3}, {%4,%5,%6,%7}, {%8,%9}, {%0,%1,%2,%3};"
                    : "+f"(c[j][0]), "+f"(c[j][1]), "+f"(c[j][2]), "+f"(c[j][3])
                    : "r"(a0), "r"(a1), "r"(a2), "r"(a3), "r"(b0), "r"(b1));
            }
        }
        __syncthreads();
    }

    int r1 = row0 + wid * 16 + g;
    int r2 = r1 + 8;
    float d1 = (r1 < M) ? g_dinv[r1] : 0.0f;
    float d2 = (r2 < M) ? g_dinv[r2] : 0.0f;
#pragma unroll
    for (int j = 0; j < 5; j++) {
        int n = j * 8 + t * 2;
        if (r1 < M)
            *(__half2*)(C + (size_t)r1 * OUTD + n) = __floats2half2_rn(c[j][0] * d1, c[j][1] * d1);
        if (r2 < M)
            *(__half2*)(C + (size_t)r2 * OUTD + n) = __floats2half2_rn(c[j][2] * d2, c[j][3] * d2);
    }
}

// ---------------- layer-1 aggregation (warp/node, fp16 gather, fp32 acc) ----
__global__ void __launch_bounds__(256) agg1_kernel(const float* __restrict__ b1, int N) {
    int warp = (blockIdx.x * blockDim.x + threadIdx.x) >> 5;
    int lane = threadIdx.x & 31;
    if (warp >= N) return;
    int d = warp;
    const __half* __restrict__ yw = g_ywh;

    uint2 u = *(const uint2*)(yw + (size_t)d * 128 + lane * 4);
    float2 f0 = __half22float2(*(__half2*)&u.x);
    float2 f1 = __half22float2(*(__half2*)&u.y);
    float4 acc = make_float4(f0.x, f0.y, f1.x, f1.y);

    int s0 = g_rs[d], s1 = g_rs[d + 1];
    for (int base = s0; base < s1; base += 32) {
        int n = s1 - base; if (n > 32) n = 32;
        int c = (lane < n) ? g_col[base + lane] : 0;
#pragma unroll 4
        for (int j = 0; j < n; j++) {
            int s = __shfl_sync(0xffffffffu, c, j);
            uint2 v = *(const uint2*)(yw + (size_t)s * 128 + lane * 4);
            float2 a = __half22float2(*(__half2*)&v.x);
            float2 b = __half22float2(*(__half2*)&v.y);
            acc.x += a.x; acc.y += a.y; acc.z += b.x; acc.w += b.y;
        }
    }
    float di = g_dinv[d];
    float4 bb = *(const float4*)(b1 + lane * 4);
    float4 o;
    o.x = fmaxf(acc.x * di + bb.x, 0.0f);
    o.y = fmaxf(acc.y * di + bb.y, 0.0f);
    o.z = fmaxf(acc.z * di + bb.z, 0.0f);
    o.w = fmaxf(acc.w * di + bb.w, 0.0f);
    *(float4*)(g_h + (size_t)d * 128 + lane * 4) = o;
}

// ---------------- layer-2 aggregation + bias + softmax (warp/node, fp16) ----
__global__ void __launch_bounds__(256) agg2_kernel(float* __restrict__ out,
                                                   const float* __restrict__ b2, int N) {
    int warp = (blockIdx.x * blockDim.x + threadIdx.x) >> 5;
    int lane = threadIdx.x & 31;
    if (warp >= N) return;
    int d = warp;
    const __half* __restrict__ ow = g_owh;

    bool act = (lane < 10);
    float4 acc = make_float4(0.f, 0.f, 0.f, 0.f);
    if (act) {
        uint2 u = *(const uint2*)(ow + (size_t)d * OUTD + lane * 4);
        float2 f0 = __half22float2(*(__half2*)&u.x);
        float2 f1 = __half22float2(*(__half2*)&u.y);
        acc = make_float4(f0.x, f0.y, f1.x, f1.y);
    }

    int s0 = g_rs[d], s1 = g_rs[d + 1];
    for (int base = s0; base < s1; base += 32) {
        int n = s1 - base; if (n > 32) n = 32;
        int c = (lane < n) ? g_col[base + lane] : 0;
#pragma unroll 4
        for (int j = 0; j < n; j++) {
            int s = __shfl_sync(0xffffffffu, c, j);
            if (act) {
                uint2 v = *(const uint2*)(ow + (size_t)s * OUTD + lane * 4);
                float2 a = __half22float2(*(__half2*)&v.x);
                float2 b = __half22float2(*(__half2*)&v.y);
                acc.x += a.x; acc.y += a.y; acc.z += b.x; acc.w += b.y;
            }
        }
    }

    float di = g_dinv[d];
    float4 l = make_float4(-1e30f, -1e30f, -1e30f, -1e30f);
    if (act) {
        float4 bb = *(const float4*)(b2 + lane * 4);
        l.x = acc.x * di + bb.x;
        l.y = acc.y * di + bb.y;
        l.z = acc.z * di + bb.z;
        l.w = acc.w * di + bb.w;
    }
    float m = fmaxf(fmaxf(l.x, l.y), fmaxf(l.z, l.w));
#pragma unroll
    for (int o = 16; o > 0; o >>= 1)
        m = fmaxf(m, __shfl_xor_sync(0xffffffffu, m, o));
    float4 e;
    e.x = __expf(l.x - m); e.y = __expf(l.y - m);
    e.z = __expf(l.z - m); e.w = __expf(l.w - m);
    float s = act ? (e.x + e.y + e.z + e.w) : 0.0f;
#pragma unroll
    for (int o = 16; o > 0; o >>= 1)
        s += __shfl_xor_sync(0xffffffffu, s, o);
    float inv = 1.0f / s;
    if (act) {
        float4 w;
        w.x = e.x * inv; w.y = e.y * inv; w.z = e.z * inv; w.w = e.w * inv;
        *(float4*)(out + (size_t)d * OUTD + lane * 4) = w;
    }
}

// ---------------- launch ----------------
extern "C" void kernel_launch(void* const* d_in, const int* in_sizes, int n_in,
                              void* d_out, int out_size) {
    const float* x  = (const float*)d_in[0];
    const void*  ei = d_in[1];
    const float* W1 = (const float*)d_in[2];
    const float* b1 = (const float*)d_in[3];
    const float* W2 = (const float*)d_in[4];
    const float* b2 = (const float*)d_in[5];
    float* out = (float*)d_out;

    int N = in_sizes[0] / IN_DIM;
    int E = in_sizes[1] / 2;
    int nb = (N + SCAN_B - 1) / SCAN_B;

    __half *ywh, *owh;
    float *h;
    cudaGetSymbolAddress((void**)&ywh, g_ywh);
    cudaGetSymbolAddress((void**)&h,   g_h);
    cudaGetSymbolAddress((void**)&owh, g_owh);

    // CSR build
    deg_kernel<<<(E + 255) / 256, 256>>>(ei, E);
    scan_p1_kernel<<<nb, SCAN_B>>>(N);
    scan_p3_kernel<<<nb, SCAN_B>>>(N, E);

    // layer 1
    gemm1_tc_kernel<<<(N + 127) / 128, 512>>>(x, W1, ywh, N);
    scatter_kernel<<<(E + 255) / 256, 256>>>(ei, E);
    agg1_kernel<<<(N * 32 + 255) / 256, 256>>>(b1, N);

    // layer 2
    gemm2_tc_kernel<<<(N + 127) / 128, 256>>>(h, W2, owh, N);
    agg2_kernel<<<(N * 32 + 255) / 256, 256>>>(out, b2, N);
}

// round 10
// speedup vs baseline: 1.0466x; 1.0466x over previous
#include <cuda_runtime.h>
#include <cuda_fp16.h>

#define IN_DIM 128
#define HIDD   128
#define OUTD   40
#define MAXN   50000
#define MAXE   800000
#define SCAN_B 256

// ---------------- scratch (device globals: allocation-free) ----------------
static __device__ __half g_ywh[MAXN * HIDD];  // fp16: dinv * (x @ W1)
static __device__ float  g_h [MAXN * HIDD];   // fp32: layer-1 output (post ReLU)
static __device__ __half g_owh[MAXN * OUTD];  // fp16: dinv * (h @ W2)
static __device__ int    g_degi[MAXN];
static __device__ float  g_dinv[MAXN];
static __device__ int    g_rs  [MAXN + 1];
static __device__ int    g_cur [MAXN];
static __device__ int    g_col [MAXE];
static __device__ int    g_bsum[(MAXN + SCAN_B - 1) / SCAN_B + 1];

// ---------------- inline per-warp dtype detection ----------------
__device__ __forceinline__ int detect_is64_warp(const int* __restrict__ ei32) {
    int lane = threadIdx.x & 31;
    int v = ei32[1 + 2 * lane];
    unsigned any = __ballot_sync(0xffffffffu, v != 0);
    return any == 0 ? 1 : 0;
}

__device__ __forceinline__ int get_idx(const void* ei, long long pos, int is64) {
    return is64 ? (int)((const long long*)ei)[pos] : ((const int*)ei)[pos];
}

// ---------------- degree histogram ----------------
__global__ void deg_kernel(const void* __restrict__ ei, int E) {
    int is64 = detect_is64_warp((const int*)ei);
    int e = blockIdx.x * blockDim.x + threadIdx.x;
    if (e >= E) return;
    int d = get_idx(ei, (long long)E + e, is64);
    atomicAdd(&g_degi[d], 1);
}

// ---------------- scan phase 1: per-block sums ----------------
__global__ void scan_p1_kernel(int N) {
    int i = blockIdx.x * blockDim.x + threadIdx.x;
    int v = (i < N) ? g_degi[i] : 0;
    int lane = threadIdx.x & 31, wid = threadIdx.x >> 5;
#pragma unroll
    for (int o = 16; o > 0; o >>= 1) v += __shfl_xor_sync(0xffffffffu, v, o);
    __shared__ int ws[SCAN_B / 32];
    if (lane == 0) ws[wid] = v;
    __syncthreads();
    if (threadIdx.x == 0) {
        int s = 0;
#pragma unroll
        for (int w = 0; w < SCAN_B / 32; w++) s += ws[w];
        g_bsum[blockIdx.x] = s;
    }
}

// ---------------- scan phase 2+3 fused ----------------
__global__ void scan_p3_kernel(int N, int E) {
    int i = blockIdx.x * blockDim.x + threadIdx.x;
    int v = (i < N) ? g_degi[i] : 0;
    int lane = threadIdx.x & 31, wid = threadIdx.x >> 5;

    __shared__ int ws[32];
    __shared__ int s_off;
    if (threadIdx.x < 32) ws[threadIdx.x] = 0;
    if (threadIdx.x == 0) s_off = 0;
    __syncthreads();

    int x = v;
#pragma unroll
    for (int o = 1; o < 32; o <<= 1) {
        int u = __shfl_up_sync(0xffffffffu, x, o);
        if (lane >= o) x += u;
    }
    if (lane == 31) ws[wid] = x;
    __syncthreads();

    if (wid == 0) {
        int w = ws[lane];
#pragma unroll
        for (int o = 1; o < 32; o <<= 1) {
            int u = __shfl_up_sync(0xffffffffu, w, o);
            if (lane >= o) w += u;
        }
        ws[lane] = w;
    } else if (wid == 1) {
        int off = 0;
        for (int j = lane; j < (int)blockIdx.x; j += 32) off += g_bsum[j];
#pragma unroll
        for (int o = 16; o > 0; o >>= 1)
            off += __shfl_xor_sync(0xffffffffu, off, o);
        if (lane == 0) s_off = off;
    }
    __syncthreads();

    int excl = x - v + (wid > 0 ? ws[wid - 1] : 0) + s_off;
    if (i < N) {
        g_rs[i]   = excl;
        g_cur[i]  = excl;
        g_dinv[i] = rsqrtf((float)(v + 1));   // +1 self loop
        g_degi[i] = 0;                        // self-clean for next replay
    }
    if (i == 0) g_rs[N] = E;
}

// ---------------- scatter: build CSR column array ----------------
__global__ void scatter_kernel(const void* __restrict__ ei, int E) {
    int is64 = detect_is64_warp((const int*)ei);
    int e = blockIdx.x * blockDim.x + threadIdx.x;
    if (e >= E) return;
    int s = get_idx(ei, e, is64);
    int d = get_idx(ei, (long long)E + e, is64);
    int pos = atomicAdd(&g_cur[d], 1);
    g_col[pos] = s;
}

// ---------------- tf32 helper (gemm2) ----------------
__device__ __forceinline__ unsigned f2tf(float f) {
    unsigned u;
    asm("cvt.rna.tf32.f32 %0, %1;" : "=r"(u) : "f"(f));
    return u;
}

__device__ __forceinline__ unsigned pack_h2(float a, float b) {
    __half2 h = __floats2half2_rn(a, b);
    return *(unsigned*)&h;
}

// ---------------- FP16 GEMM1 (256 thr, 8 warps x [32 rows x 64 cols]) -------
// g_ywh = half( dinv[r] * (A[M,128] @ B[128,128]) ), mma m16n8k16 f16->f32.
// Smem words are packed half2 along k: As[row][kw] LDA=20, Bs[kw][n] LDB=136.
__global__ void __launch_bounds__(256) gemm1_tc_kernel(const float* __restrict__ A,
                                                       const float* __restrict__ B,
                                                       __half* __restrict__ C, int M) {
    __shared__ unsigned As[128 * 20];   // [row][kw 0..15], pad to 20
    __shared__ unsigned Bs[16 * 136];   // [kw][n 0..127], pad to 136

    const int tid  = threadIdx.x;
    const int wid  = tid >> 5;
    const int lane = tid & 31;
    const int g    = lane >> 2;
    const int t    = lane & 3;
    const int wr   = wid & 3;          // row-group (32 rows)
    const int wn   = wid >> 2;         // n-half (64 cols)
    const int row0 = blockIdx.x * 128;

    float c[2][8][4];
#pragma unroll
    for (int mi = 0; mi < 2; mi++)
#pragma unroll
        for (int j = 0; j < 8; j++)
#pragma unroll
            for (int q = 0; q < 4; q++) c[mi][j][q] = 0.0f;

    for (int k0 = 0; k0 < 128; k0 += 32) {
        // stage A: 128 rows x 32 k (f32) -> packed half2 words
#pragma unroll
        for (int f = 0; f < 4; f++) {
            int l4  = tid + f * 256;          // 1024 float4 slots
            int row = l4 >> 3;
            int kq  = (l4 & 7) * 4;           // k offset in chunk, mult of 4
            float4 v = make_float4(0.f, 0.f, 0.f, 0.f);
            if (row0 + row < M)
                v = *(const float4*)(A + (size_t)(row0 + row) * 128 + k0 + kq);
            As[row * 20 + (kq >> 1)    ] = pack_h2(v.x, v.y);
            As[row * 20 + (kq >> 1) + 1] = pack_h2(v.z, v.w);
        }
        // stage B: 32 k x 128 n (f32), transposed-packed along k
#pragma unroll
        for (int w = 0; w < 8; w++) {
            int idx = tid + w * 256;          // 2048 word slots
            int kw  = idx >> 7;               // 0..15
            int n   = idx & 127;
            float b0 = B[(size_t)(k0 + 2 * kw)     * 128 + n];
            float b1 = B[(size_t)(k0 + 2 * kw + 1) * 128 + n];
            Bs[kw * 136 + n] = pack_h2(b0, b1);
        }
        __syncthreads();

#pragma unroll
        for (int kc = 0; kc < 2; kc++) {      // two k16 steps per 32-chunk
            unsigned a[2][4];
#pragma unroll
            for (int mi = 0; mi < 2; mi++) {
                int R = wr * 32 + mi * 16;
                a[mi][0] = As[(R + g    ) * 20 + kc * 8 + t    ];
                a[mi][1] = As[(R + 8 + g) * 20 + kc * 8 + t    ];
                a[mi][2] = As[(R + g    ) * 20 + kc * 8 + t + 4];
                a[mi][3] = As[(R + 8 + g) * 20 + kc * 8 + t + 4];
            }
#pragma unroll
            for (int j = 0; j < 8; j++) {
                int n = wn * 64 + j * 8 + g;
                unsigned b0 = Bs[(kc * 8 + t    ) * 136 + n];
                unsigned b1 = Bs[(kc * 8 + t + 4) * 136 + n];
#pragma unroll
                for (int mi = 0; mi < 2; mi++) {
                    asm volatile(
                        "mma.sync.aligned.m16n8k16.row.col.f32.f16.f16.f32 "
                        "{%0,%1,%2,%3}, {%4,%5,%6,%7}, {%8,%9}, {%0,%1,%2,%3};"
                        : "+f"(c[mi][j][0]), "+f"(c[mi][j][1]),
                          "+f"(c[mi][j][2]), "+f"(c[mi][j][3])
                        : "r"(a[mi][0]), "r"(a[mi][1]), "r"(a[mi][2]), "r"(a[mi][3]),
                          "r"(b0), "r"(b1));
                }
            }
        }
        __syncthreads();
    }

    // epilogue: scale rows by dinv, half2 stores
#pragma unroll
    for (int mi = 0; mi < 2; mi++) {
        int r1 = row0 + wr * 32 + mi * 16 + g;
        int r2 = r1 + 8;
        float d1 = (r1 < M) ? g_dinv[r1] : 0.0f;
        float d2 = (r2 < M) ? g_dinv[r2] : 0.0f;
#pragma unroll
        for (int j = 0; j < 8; j++) {
            int n = wn * 64 + j * 8 + t * 2;
            if (r1 < M)
                *(__half2*)(C + (size_t)r1 * 128 + n) =
                    __floats2half2_rn(c[mi][j][0] * d1, c[mi][j][1] * d1);
            if (r2 < M)
                *(__half2*)(C + (size_t)r2 * 128 + n) =
                    __floats2half2_rn(c[mi][j][2] * d2, c[mi][j][3] * d2);
        }
    }
}

// ---------------- TF32 GEMM2: g_owh = half( dinv[r] * (h[M,128] @ W2[128,40]) )
__global__ void __launch_bounds__(256) gemm2_tc_kernel(const float* __restrict__ A,
                                                       const float* __restrict__ B,
                                                       __half* __restrict__ C, int M) {
    __shared__ unsigned As[32][136];   // [k][row], per 32-k chunk
    __shared__ unsigned Bs[128][48];   // full B [k][n], staged once

    const int tid  = threadIdx.x;
    const int wid  = tid >> 5;
    const int lane = tid & 31;
    const int g    = lane >> 2;
    const int t    = lane & 3;
    const int row0 = blockIdx.x * 128;

    for (int i = tid; i < 128 * OUTD; i += 256) {
        int k = i / OUTD, n = i - k * OUTD;
        Bs[k][n] = f2tf(B[(size_t)k * OUTD + n]);
    }

    float c[5][4];
#pragma unroll
    for (int j = 0; j < 5; j++)
#pragma unroll
        for (int q = 0; q < 4; q++) c[j][q] = 0.0f;

    for (int k0 = 0; k0 < 128; k0 += 32) {
#pragma unroll
        for (int f = 0; f < 4; f++) {
            int l4  = tid + f * 256;
            int row = l4 >> 3;
            int kq  = (l4 & 7) * 4;
            float4 v = make_float4(0.f, 0.f, 0.f, 0.f);
            if (row0 + row < M)
                v = *(const float4*)(A + (size_t)(row0 + row) * 128 + k0 + kq);
            As[kq + 0][row] = f2tf(v.x);
            As[kq + 1][row] = f2tf(v.y);
            As[kq + 2][row] = f2tf(v.z);
            As[kq + 3][row] = f2tf(v.w);
        }
        __syncthreads();

#pragma unroll
        for (int kk = 0; kk < 4; kk++) {
            unsigned a0 = As[kk * 8 + t    ][wid * 16 + g    ];
            unsigned a1 = As[kk * 8 + t    ][wid * 16 + g + 8];
            unsigned a2 = As[kk * 8 + t + 4][wid * 16 + g    ];
            unsigned a3 = As[kk * 8 + t + 4][wid * 16 + g + 8];
#pragma unroll
            for (int j = 0; j < 5; j++) {
                unsigned b0 = Bs[k0 + kk * 8 + t    ][j * 8 + g];
                unsigned b1 = Bs[k0 + kk * 8 + t + 4][j * 8 + g];
                asm volatile(
                    "mma.sync.aligned.m16n8k8.row.col.f32.tf32.tf32.f32 "
                    "{%0,%1,%2,%3}, {%4,%5,%6,%7}, {%8,%9}, {%0,%1,%2,%3};"
                    : "+f"(c[j][0]), "+f"(c[j][1]), "+f"(c[j][2]), "+f"(c[j][3])
                    : "r"(a0), "r"(a1), "r"(a2), "r"(a3), "r"(b0), "r"(b1));
            }
        }
        __syncthreads();
    }

    int r1 = row0 + wid * 16 + g;
    int r2 = r1 + 8;
    float d1 = (r1 < M) ? g_dinv[r1] : 0.0f;
    float d2 = (r2 < M) ? g_dinv[r2] : 0.0f;
#pragma unroll
    for (int j = 0; j < 5; j++) {
        int n = j * 8 + t * 2;
        if (r1 < M)
            *(__half2*)(C + (size_t)r1 * OUTD + n) = __floats2half2_rn(c[j][0] * d1, c[j][1] * d1);
        if (r2 < M)
            *(__half2*)(C + (size_t)r2 * OUTD + n) = __floats2half2_rn(c[j][2] * d2, c[j][3] * d2);
    }
}

// ---------------- layer-1 aggregation (warp/node, fp16 gather, fp32 acc) ----
__global__ void __launch_bounds__(256) agg1_kernel(const float* __restrict__ b1, int N) {
    int warp = (blockIdx.x * blockDim.x + threadIdx.x) >> 5;
    int lane = threadIdx.x & 31;
    if (warp >= N) return;
    int d = warp;
    const __half* __restrict__ yw = g_ywh;

    uint2 u = *(const uint2*)(yw + (size_t)d * 128 + lane * 4);
    float2 f0 = __half22float2(*(__half2*)&u.x);
    float2 f1 = __half22float2(*(__half2*)&u.y);
    float4 acc = make_float4(f0.x, f0.y, f1.x, f1.y);

    int s0 = g_rs[d], s1 = g_rs[d + 1];
    for (int base = s0; base < s1; base += 32) {
        int n = s1 - base; if (n > 32) n = 32;
        int c = (lane < n) ? g_col[base + lane] : 0;
#pragma unroll 4
        for (int j = 0; j < n; j++) {
            int s = __shfl_sync(0xffffffffu, c, j);
            uint2 v = *(const uint2*)(yw + (size_t)s * 128 + lane * 4);
            float2 a = __half22float2(*(__half2*)&v.x);
            float2 b = __half22float2(*(__half2*)&v.y);
            acc.x += a.x; acc.y += a.y; acc.z += b.x; acc.w += b.y;
        }
    }
    float di = g_dinv[d];
    float4 bb = *(const float4*)(b1 + lane * 4);
    float4 o;
    o.x = fmaxf(acc.x * di + bb.x, 0.0f);
    o.y = fmaxf(acc.y * di + bb.y, 0.0f);
    o.z = fmaxf(acc.z * di + bb.z, 0.0f);
    o.w = fmaxf(acc.w * di + bb.w, 0.0f);
    *(float4*)(g_h + (size_t)d * 128 + lane * 4) = o;
}

// ---------------- layer-2 aggregation + bias + softmax (warp/node, fp16) ----
__global__ void __launch_bounds__(256) agg2_kernel(float* __restrict__ out,
                                                   const float* __restrict__ b2, int N) {
    int warp = (blockIdx.x * blockDim.x + threadIdx.x) >> 5;
    int lane = threadIdx.x & 31;
    if (warp >= N) return;
    int d = warp;
    const __half* __restrict__ ow = g_owh;

    bool act = (lane < 10);
    float4 acc = make_float4(0.f, 0.f, 0.f, 0.f);
    if (act) {
        uint2 u = *(const uint2*)(ow + (size_t)d * OUTD + lane * 4);
        float2 f0 = __half22float2(*(__half2*)&u.x);
        float2 f1 = __half22float2(*(__half2*)&u.y);
        acc = make_float4(f0.x, f0.y, f1.x, f1.y);
    }

    int s0 = g_rs[d], s1 = g_rs[d + 1];
    for (int base = s0; base < s1; base += 32) {
        int n = s1 - base; if (n > 32) n = 32;
        int c = (lane < n) ? g_col[base + lane] : 0;
#pragma unroll 4
        for (int j = 0; j < n; j++) {
            int s = __shfl_sync(0xffffffffu, c, j);
            if (act) {
                uint2 v = *(const uint2*)(ow + (size_t)s * OUTD + lane * 4);
                float2 a = __half22float2(*(__half2*)&v.x);
                float2 b = __half22float2(*(__half2*)&v.y);
                acc.x += a.x; acc.y += a.y; acc.z += b.x; acc.w += b.y;
            }
        }
    }

    float di = g_dinv[d];
    float4 l = make_float4(-1e30f, -1e30f, -1e30f, -1e30f);
    if (act) {
        float4 bb = *(const float4*)(b2 + lane * 4);
        l.x = acc.x * di + bb.x;
        l.y = acc.y * di + bb.y;
        l.z = acc.z * di + bb.z;
        l.w = acc.w * di + bb.w;
    }
    float m = fmaxf(fmaxf(l.x, l.y), fmaxf(l.z, l.w));
#pragma unroll
    for (int o = 16; o > 0; o >>= 1)
        m = fmaxf(m, __shfl_xor_sync(0xffffffffu, m, o));
    float4 e;
    e.x = __expf(l.x - m); e.y = __expf(l.y - m);
    e.z = __expf(l.z - m); e.w = __expf(l.w - m);
    float s = act ? (e.x + e.y + e.z + e.w) : 0.0f;
#pragma unroll
    for (int o = 16; o > 0; o >>= 1)
        s += __shfl_xor_sync(0xffffffffu, s, o);
    float inv = 1.0f / s;
    if (act) {
        float4 w;
        w.x = e.x * inv; w.y = e.y * inv; w.z = e.z * inv; w.w = e.w * inv;
        *(float4*)(out + (size_t)d * OUTD + lane * 4) = w;
    }
}

// ---------------- launch ----------------
extern "C" void kernel_launch(void* const* d_in, const int* in_sizes, int n_in,
                              void* d_out, int out_size) {
    const float* x  = (const float*)d_in[0];
    const void*  ei = d_in[1];
    const float* W1 = (const float*)d_in[2];
    const float* b1 = (const float*)d_in[3];
    const float* W2 = (const float*)d_in[4];
    const float* b2 = (const float*)d_in[5];
    float* out = (float*)d_out;

    int N = in_sizes[0] / IN_DIM;
    int E = in_sizes[1] / 2;
    int nb = (N + SCAN_B - 1) / SCAN_B;

    __half *ywh, *owh;
    float *h;
    cudaGetSymbolAddress((void**)&ywh, g_ywh);
    cudaGetSymbolAddress((void**)&h,   g_h);
    cudaGetSymbolAddress((void**)&owh, g_owh);

    // CSR build
    deg_kernel<<<(E + 255) / 256, 256>>>(ei, E);
    scan_p1_kernel<<<nb, SCAN_B>>>(N);
    scan_p3_kernel<<<nb, SCAN_B>>>(N, E);

    // layer 1
    gemm1_tc_kernel<<<(N + 127) / 128, 256>>>(x, W1, ywh, N);
    scatter_kernel<<<(E + 255) / 256, 256>>>(ei, E);
    agg1_kernel<<<(N * 32 + 255) / 256, 256>>>(b1, N);

    // layer 2
    gemm2_tc_kernel<<<(N + 127) / 128, 256>>>(h, W2, owh, N);
    agg2_kernel<<<(N * 32 + 255) / 256, 256>>>(out, b2, N);
}

// round 11
// speedup vs baseline: 1.1055x; 1.0563x over previous
#include <cuda_runtime.h>
#include <cuda_fp16.h>

#define IN_DIM 128
#define HIDD   128
#define OUTD   40
#define MAXN   50000
#define MAXE   800000
#define SCAN_B 256

// ---------------- scratch (device globals: allocation-free) ----------------
static __device__ __half g_ywh[MAXN * HIDD];  // fp16: dinv * (x @ W1)
static __device__ float  g_h [MAXN * HIDD];   // fp32: layer-1 output (post ReLU)
static __device__ __half g_owh[MAXN * OUTD];  // fp16: dinv * (h @ W2)
static __device__ int    g_degi[MAXN];
static __device__ float  g_dinv[MAXN];
static __device__ int    g_rs  [MAXN + 1];
static __device__ int    g_cur [MAXN];
static __device__ int    g_col [MAXE];
static __device__ int    g_bsum[(MAXN + SCAN_B - 1) / SCAN_B + 1];

// ---------------- inline per-warp dtype detection ----------------
__device__ __forceinline__ int detect_is64_warp(const int* __restrict__ ei32) {
    int lane = threadIdx.x & 31;
    int v = ei32[1 + 2 * lane];
    unsigned any = __ballot_sync(0xffffffffu, v != 0);
    return any == 0 ? 1 : 0;
}

__device__ __forceinline__ int get_idx(const void* ei, long long pos, int is64) {
    return is64 ? (int)((const long long*)ei)[pos] : ((const int*)ei)[pos];
}

// ---------------- degree histogram ----------------
__global__ void deg_kernel(const void* __restrict__ ei, int E) {
    int is64 = detect_is64_warp((const int*)ei);
    int e = blockIdx.x * blockDim.x + threadIdx.x;
    if (e >= E) return;
    int d = get_idx(ei, (long long)E + e, is64);
    atomicAdd(&g_degi[d], 1);
}

// ---------------- scan phase 1: per-block sums ----------------
__global__ void scan_p1_kernel(int N) {
    int i = blockIdx.x * blockDim.x + threadIdx.x;
    int v = (i < N) ? g_degi[i] : 0;
    int lane = threadIdx.x & 31, wid = threadIdx.x >> 5;
#pragma unroll
    for (int o = 16; o > 0; o >>= 1) v += __shfl_xor_sync(0xffffffffu, v, o);
    __shared__ int ws[SCAN_B / 32];
    if (lane == 0) ws[wid] = v;
    __syncthreads();
    if (threadIdx.x == 0) {
        int s = 0;
#pragma unroll
        for (int w = 0; w < SCAN_B / 32; w++) s += ws[w];
        g_bsum[blockIdx.x] = s;
    }
}

// ---------------- scan phase 2+3 fused ----------------
__global__ void scan_p3_kernel(int N, int E) {
    int i = blockIdx.x * blockDim.x + threadIdx.x;
    int v = (i < N) ? g_degi[i] : 0;
    int lane = threadIdx.x & 31, wid = threadIdx.x >> 5;

    __shared__ int ws[32];
    __shared__ int s_off;
    if (threadIdx.x < 32) ws[threadIdx.x] = 0;
    if (threadIdx.x == 0) s_off = 0;
    __syncthreads();

    int x = v;
#pragma unroll
    for (int o = 1; o < 32; o <<= 1) {
        int u = __shfl_up_sync(0xffffffffu, x, o);
        if (lane >= o) x += u;
    }
    if (lane == 31) ws[wid] = x;
    __syncthreads();

    if (wid == 0) {
        int w = ws[lane];
#pragma unroll
        for (int o = 1; o < 32; o <<= 1) {
            int u = __shfl_up_sync(0xffffffffu, w, o);
            if (lane >= o) w += u;
        }
        ws[lane] = w;
    } else if (wid == 1) {
        int off = 0;
        for (int j = lane; j < (int)blockIdx.x; j += 32) off += g_bsum[j];
#pragma unroll
        for (int o = 16; o > 0; o >>= 1)
            off += __shfl_xor_sync(0xffffffffu, off, o);
        if (lane == 0) s_off = off;
    }
    __syncthreads();

    int excl = x - v + (wid > 0 ? ws[wid - 1] : 0) + s_off;
    if (i < N) {
        g_rs[i]   = excl;
        g_cur[i]  = excl;
        g_dinv[i] = rsqrtf((float)(v + 1));   // +1 self loop
        g_degi[i] = 0;                        // self-clean for next replay
    }
    if (i == 0) g_rs[N] = E;
}

// ---------------- scatter: build CSR column array ----------------
__global__ void scatter_kernel(const void* __restrict__ ei, int E) {
    int is64 = detect_is64_warp((const int*)ei);
    int e = blockIdx.x * blockDim.x + threadIdx.x;
    if (e >= E) return;
    int s = get_idx(ei, e, is64);
    int d = get_idx(ei, (long long)E + e, is64);
    int pos = atomicAdd(&g_cur[d], 1);
    g_col[pos] = s;
}

// ---------------- helpers ----------------
__device__ __forceinline__ unsigned f2tf(float f) {
    unsigned u;
    asm("cvt.rna.tf32.f32 %0, %1;" : "=r"(u) : "f"(f));
    return u;
}

__device__ __forceinline__ unsigned pack_h2(float a, float b) {
    __half2 h = __floats2half2_rn(a, b);
    return *(unsigned*)&h;
}

// ---------------- FP16 GEMM1 (256 thr, 8 warps x [32 rows x 64 cols]) -------
// g_ywh = half( dinv[r] * (A[M,128] @ B[128,128]) ), mma m16n8k16 f16->f32.
// B staged to smem ONCE per block; A tile staged whole (1 sync), then all
// 8 k16 steps run uninterrupted. Dynamic smem: A 128x68w + B 64x136w = 68KB.
#define G1_LDA 68
#define G1_LDB 136
#define G1_SMEM ((128 * G1_LDA + 64 * G1_LDB) * 4)

__global__ void __launch_bounds__(256, 2) gemm1_tc_kernel(const float* __restrict__ A,
                                                          const float* __restrict__ B,
                                                          __half* __restrict__ C, int M) {
    extern __shared__ unsigned sm1[];
    unsigned* As = sm1;                    // [row][kw 0..63] pad 68
    unsigned* Bs = sm1 + 128 * G1_LDA;     // [kw 0..63][n 0..127] pad 136

    const int tid  = threadIdx.x;
    const int wid  = tid >> 5;
    const int lane = tid & 31;
    const int g    = lane >> 2;
    const int t    = lane & 3;
    const int wr   = wid & 3;          // row-group (32 rows)
    const int wn   = wid >> 2;         // n-half (64 cols)
    const int row0 = blockIdx.x * 128;

    // stage ALL of B (W1) once: 64 kw x 128 n packed half2 along k
    for (int idx = tid; idx < 64 * 128; idx += 256) {
        int kw = idx >> 7, n = idx & 127;
        float b0 = B[(size_t)(2 * kw)     * 128 + n];
        float b1 = B[(size_t)(2 * kw + 1) * 128 + n];
        Bs[kw * G1_LDB + n] = pack_h2(b0, b1);
    }

    // stage whole A tile: 128 rows x 32 float4 slots, 16 independent LDG/thread
#pragma unroll
    for (int f = 0; f < 16; f++) {
        int l4  = tid + f * 256;           // 0..4095
        int row = l4 >> 5;
        int fq  = l4 & 31;                 // float4 index in row
        float4 v = make_float4(0.f, 0.f, 0.f, 0.f);
        if (row0 + row < M)
            v = *(const float4*)(A + (size_t)(row0 + row) * 128 + fq * 4);
        As[row * G1_LDA + fq * 2    ] = pack_h2(v.x, v.y);
        As[row * G1_LDA + fq * 2 + 1] = pack_h2(v.z, v.w);
    }
    __syncthreads();

    float c[2][8][4];
#pragma unroll
    for (int mi = 0; mi < 2; mi++)
#pragma unroll
        for (int j = 0; j < 8; j++)
#pragma unroll
            for (int q = 0; q < 4; q++) c[mi][j][q] = 0.0f;

#pragma unroll
    for (int kh = 0; kh < 8; kh++) {       // 8 k16 steps cover K=128
        unsigned a[2][4];
#pragma unroll
        for (int mi = 0; mi < 2; mi++) {
            int R = wr * 32 + mi * 16;
            a[mi][0] = As[(R + g    ) * G1_LDA + kh * 8 + t    ];
            a[mi][1] = As[(R + 8 + g) * G1_LDA + kh * 8 + t    ];
            a[mi][2] = As[(R + g    ) * G1_LDA + kh * 8 + t + 4];
            a[mi][3] = As[(R + 8 + g) * G1_LDA + kh * 8 + t + 4];
        }
#pragma unroll
        for (int j = 0; j < 8; j++) {
            int n = wn * 64 + j * 8 + g;
            unsigned b0 = Bs[(kh * 8 + t    ) * G1_LDB + n];
            unsigned b1 = Bs[(kh * 8 + t + 4) * G1_LDB + n];
#pragma unroll
            for (int mi = 0; mi < 2; mi++) {
                asm volatile(
                    "mma.sync.aligned.m16n8k16.row.col.f32.f16.f16.f32 "
                    "{%0,%1,%2,%3}, {%4,%5,%6,%7}, {%8,%9}, {%0,%1,%2,%3};"
                    : "+f"(c[mi][j][0]), "+f"(c[mi][j][1]),
                      "+f"(c[mi][j][2]), "+f"(c[mi][j][3])
                    : "r"(a[mi][0]), "r"(a[mi][1]), "r"(a[mi][2]), "r"(a[mi][3]),
                      "r"(b0), "r"(b1));
            }
        }
    }

    // epilogue: scale rows by dinv, half2 stores
#pragma unroll
    for (int mi = 0; mi < 2; mi++) {
        int r1 = row0 + wr * 32 + mi * 16 + g;
        int r2 = r1 + 8;
        float d1 = (r1 < M) ? g_dinv[r1] : 0.0f;
        float d2 = (r2 < M) ? g_dinv[r2] : 0.0f;
#pragma unroll
        for (int j = 0; j < 8; j++) {
            int n = wn * 64 + j * 8 + t * 2;
            if (r1 < M)
                *(__half2*)(C + (size_t)r1 * 128 + n) =
                    __floats2half2_rn(c[mi][j][0] * d1, c[mi][j][1] * d1);
            if (r2 < M)
                *(__half2*)(C + (size_t)r2 * 128 + n) =
                    __floats2half2_rn(c[mi][j][2] * d2, c[mi][j][3] * d2);
        }
    }
}

// ---------------- TF32 GEMM2: g_owh = half( dinv[r] * (h[M,128] @ W2[128,40]) )
__global__ void __launch_bounds__(256) gemm2_tc_kernel(const float* __restrict__ A,
                                                       const float* __restrict__ B,
                                                       __half* __restrict__ C, int M) {
    __shared__ unsigned As[32][136];   // [k][row], per 32-k chunk
    __shared__ unsigned Bs[128][48];   // full B [k][n], staged once

    const int tid  = threadIdx.x;
    const int wid  = tid >> 5;
    const int lane = tid & 31;
    const int g    = lane >> 2;
    const int t    = lane & 3;
    const int row0 = blockIdx.x * 128;

    for (int i = tid; i < 128 * OUTD; i += 256) {
        int k = i / OUTD, n = i - k * OUTD;
        Bs[k][n] = f2tf(B[(size_t)k * OUTD + n]);
    }

    float c[5][4];
#pragma unroll
    for (int j = 0; j < 5; j++)
#pragma unroll
        for (int q = 0; q < 4; q++) c[j][q] = 0.0f;

    for (int k0 = 0; k0 < 128; k0 += 32) {
#pragma unroll
        for (int f = 0; f < 4; f++) {
            int l4  = tid + f * 256;
            int row = l4 >> 3;
            int kq  = (l4 & 7) * 4;
            float4 v = make_float4(0.f, 0.f, 0.f, 0.f);
            if (row0 + row < M)
                v = *(const float4*)(A + (size_t)(row0 + row) * 128 + k0 + kq);
            As[kq + 0][row] = f2tf(v.x);
            As[kq + 1][row] = f2tf(v.y);
            As[kq + 2][row] = f2tf(v.z);
            As[kq + 3][row] = f2tf(v.w);
        }
        __syncthreads();

#pragma unroll
        for (int kk = 0; kk < 4; kk++) {
            unsigned a0 = As[kk * 8 + t    ][wid * 16 + g    ];
            unsigned a1 = As[kk * 8 + t    ][wid * 16 + g + 8];
            unsigned a2 = As[kk * 8 + t + 4][wid * 16 + g    ];
            unsigned a3 = As[kk * 8 + t + 4][wid * 16 + g + 8];
#pragma unroll
            for (int j = 0; j < 5; j++) {
                unsigned b0 = Bs[k0 + kk * 8 + t    ][j * 8 + g];
                unsigned b1 = Bs[k0 + kk * 8 + t + 4][j * 8 + g];
                asm volatile(
                    "mma.sync.aligned.m16n8k8.row.col.f32.tf32.tf32.f32 "
                    "{%0,%1,%2,%3}, {%4,%5,%6,%7}, {%8,%9}, {%0,%1,%2,%3};"
                    : "+f"(c[j][0]), "+f"(c[j][1]), "+f"(c[j][2]), "+f"(c[j][3])
                    : "r"(a0), "r"(a1), "r"(a2), "r"(a3), "r"(b0), "r"(b1));
            }
        }
        __syncthreads();
    }

    int r1 = row0 + wid * 16 + g;
    int r2 = r1 + 8;
    float d1 = (r1 < M) ? g_dinv[r1] : 0.0f;
    float d2 = (r2 < M) ? g_dinv[r2] : 0.0f;
#pragma unroll
    for (int j = 0; j < 5; j++) {
        int n = j * 8 + t * 2;
        if (r1 < M)
            *(__half2*)(C + (size_t)r1 * OUTD + n) = __floats2half2_rn(c[j][0] * d1, c[j][1] * d1);
        if (r2 < M)
            *(__half2*)(C + (size_t)r2 * OUTD + n) = __floats2half2_rn(c[j][2] * d2, c[j][3] * d2);
    }
}

// ---------------- layer-1 aggregation (warp/node, fp16 gather, fp32 acc) ----
__global__ void __launch_bounds__(256) agg1_kernel(const float* __restrict__ b1, int N) {
    int warp = (blockIdx.x * blockDim.x + threadIdx.x) >> 5;
    int lane = threadIdx.x & 31;
    if (warp >= N) return;
    int d = warp;
    const __half* __restrict__ yw = g_ywh;

    uint2 u = *(const uint2*)(yw + (size_t)d * 128 + lane * 4);
    float2 f0 = __half22float2(*(__half2*)&u.x);
    float2 f1 = __half22float2(*(__half2*)&u.y);
    float4 acc = make_float4(f0.x, f0.y, f1.x, f1.y);

    int s0 = g_rs[d], s1 = g_rs[d + 1];
    for (int base = s0; base < s1; base += 32) {
        int n = s1 - base; if (n > 32) n = 32;
        int c = (lane < n) ? g_col[base + lane] : 0;
#pragma unroll 4
        for (int j = 0; j < n; j++) {
            int s = __shfl_sync(0xffffffffu, c, j);
            uint2 v = *(const uint2*)(yw + (size_t)s * 128 + lane * 4);
            float2 a = __half22float2(*(__half2*)&v.x);
            float2 b = __half22float2(*(__half2*)&v.y);
            acc.x += a.x; acc.y += a.y; acc.z += b.x; acc.w += b.y;
        }
    }
    float di = g_dinv[d];
    float4 bb = *(const float4*)(b1 + lane * 4);
    float4 o;
    o.x = fmaxf(acc.x * di + bb.x, 0.0f);
    o.y = fmaxf(acc.y * di + bb.y, 0.0f);
    o.z = fmaxf(acc.z * di + bb.z, 0.0f);
    o.w = fmaxf(acc.w * di + bb.w, 0.0f);
    *(float4*)(g_h + (size_t)d * 128 + lane * 4) = o;
}

// ---------------- layer-2 aggregation + bias + softmax (warp/node, fp16) ----
__global__ void __launch_bounds__(256) agg2_kernel(float* __restrict__ out,
                                                   const float* __restrict__ b2, int N) {
    int warp = (blockIdx.x * blockDim.x + threadIdx.x) >> 5;
    int lane = threadIdx.x & 31;
    if (warp >= N) return;
    int d = warp;
    const __half* __restrict__ ow = g_owh;

    bool act = (lane < 10);
    float4 acc = make_float4(0.f, 0.f, 0.f, 0.f);
    if (act) {
        uint2 u = *(const uint2*)(ow + (size_t)d * OUTD + lane * 4);
        float2 f0 = __half22float2(*(__half2*)&u.x);
        float2 f1 = __half22float2(*(__half2*)&u.y);
        acc = make_float4(f0.x, f0.y, f1.x, f1.y);
    }

    int s0 = g_rs[d], s1 = g_rs[d + 1];
    for (int base = s0; base < s1; base += 32) {
        int n = s1 - base; if (n > 32) n = 32;
        int c = (lane < n) ? g_col[base + lane] : 0;
#pragma unroll 4
        for (int j = 0; j < n; j++) {
            int s = __shfl_sync(0xffffffffu, c, j);
            if (act) {
                uint2 v = *(const uint2*)(ow + (size_t)s * OUTD + lane * 4);
                float2 a = __half22float2(*(__half2*)&v.x);
                float2 b = __half22float2(*(__half2*)&v.y);
                acc.x += a.x; acc.y += a.y; acc.z += b.x; acc.w += b.y;
            }
        }
    }

    float di = g_dinv[d];
    float4 l = make_float4(-1e30f, -1e30f, -1e30f, -1e30f);
    if (act) {
        float4 bb = *(const float4*)(b2 + lane * 4);
        l.x = acc.x * di + bb.x;
        l.y = acc.y * di + bb.y;
        l.z = acc.z * di + bb.z;
        l.w = acc.w * di + bb.w;
    }
    float m = fmaxf(fmaxf(l.x, l.y), fmaxf(l.z, l.w));
#pragma unroll
    for (int o = 16; o > 0; o >>= 1)
        m = fmaxf(m, __shfl_xor_sync(0xffffffffu, m, o));
    float4 e;
    e.x = __expf(l.x - m); e.y = __expf(l.y - m);
    e.z = __expf(l.z - m); e.w = __expf(l.w - m);
    float s = act ? (e.x + e.y + e.z + e.w) : 0.0f;
#pragma unroll
    for (int o = 16; o > 0; o >>= 1)
        s += __shfl_xor_sync(0xffffffffu, s, o);
    float inv = 1.0f / s;
    if (act) {
        float4 w;
        w.x = e.x * inv; w.y = e.y * inv; w.z = e.z * inv; w.w = e.w * inv;
        *(float4*)(out + (size_t)d * OUTD + lane * 4) = w;
    }
}

// ---------------- launch ----------------
extern "C" void kernel_launch(void* const* d_in, const int* in_sizes, int n_in,
                              void* d_out, int out_size) {
    const float* x  = (const float*)d_in[0];
    const void*  ei = d_in[1];
    const float* W1 = (const float*)d_in[2];
    const float* b1 = (const float*)d_in[3];
    const float* W2 = (const float*)d_in[4];
    const float* b2 = (const float*)d_in[5];
    float* out = (float*)d_out;

    int N = in_sizes[0] / IN_DIM;
    int E = in_sizes[1] / 2;
    int nb = (N + SCAN_B - 1) / SCAN_B;

    __half *ywh, *owh;
    float *h;
    cudaGetSymbolAddress((void**)&ywh, g_ywh);
    cudaGetSymbolAddress((void**)&h,   g_h);
    cudaGetSymbolAddress((void**)&owh, g_owh);

    static int smem_set = 0;
    if (!smem_set) {
        cudaFuncSetAttribute(gemm1_tc_kernel,
                             cudaFuncAttributeMaxDynamicSharedMemorySize, G1_SMEM);
        smem_set = 1;
    }

    // CSR build
    deg_kernel<<<(E + 255) / 256, 256>>>(ei, E);
    scan_p1_kernel<<<nb, SCAN_B>>>(N);
    scan_p3_kernel<<<nb, SCAN_B>>>(N, E);

    // layer 1
    gemm1_tc_kernel<<<(N + 127) / 128, 256, G1_SMEM>>>(x, W1, ywh, N);
    scatter_kernel<<<(E + 255) / 256, 256>>>(ei, E);
    agg1_kernel<<<(N * 32 + 255) / 256, 256>>>(b1, N);

    // layer 2
    gemm2_tc_kernel<<<(N + 127) / 128, 256>>>(h, W2, owh, N);
    agg2_kernel<<<(N * 32 + 255) / 256, 256>>>(out, b2, N);
}